// round 5
// baseline (speedup 1.0000x reference)
#include <cuda_runtime.h>
#include <cuda_bf16.h>
#include <cstdint>

#define TOKENS 8192
#define DIM    1024
#define NE     8
#define HID    2730
#define HP     2816
#define NPAIR  (TOKENS*2)
#define HROWS  (NPAIR + 256)

#define SWZ(o) ((o) ^ (((o) >> 3) & 0x70))

#define BM1 256
#define BN1 64
#define ST1 98304   // stage bytes: Ah 0, Al 32768, W1h 65536, W1l 73728, W3h 81920, W3l 90112
#define BM2 256
#define BN2 128
#define ST2 98304   // Ah 0, Al 32768, Bh 65536, Bl 81920

// ---------------- device scratch ----------------
__device__ int   g_count[NE];
__device__ int   g_off[NE];
__device__ int   g_tokens[NE][TOKENS];
__device__ float g_wts[NE][TOKENS];
__device__ float g_probsum[NE];

__device__ __nv_bfloat16 g_XH[TOKENS*DIM];
__device__ __nv_bfloat16 g_XL[TOKENS*DIM];
__device__ __nv_bfloat16 g_W1H[NE*HP*DIM];
__device__ __nv_bfloat16 g_W1L[NE*HP*DIM];
__device__ __nv_bfloat16 g_W3H[NE*HP*DIM];
__device__ __nv_bfloat16 g_W3L[NE*HP*DIM];
__device__ __nv_bfloat16 g_W2H[NE*DIM*HP];
__device__ __nv_bfloat16 g_W2L[NE*DIM*HP];
__device__ __nv_bfloat16 g_HH[(size_t)HROWS*HP];
__device__ __nv_bfloat16 g_HL[(size_t)HROWS*HP];

// ---------------- helpers ----------------
__device__ __forceinline__ uint32_t s2u(const void* p) {
    uint32_t a;
    asm("{ .reg .u64 t; cvta.to.shared.u64 t, %1; cvt.u32.u64 %0, t; }" : "=r"(a) : "l"(p));
    return a;
}
__device__ __forceinline__ void cpa16(uint32_t dst, const void* src) {
    asm volatile("cp.async.cg.shared.global [%0], [%1], 16;" :: "r"(dst), "l"(src));
}
__device__ __forceinline__ void cp_commit() {
    asm volatile("cp.async.commit_group;" ::: "memory");
}
__device__ __forceinline__ void cp_wait1() {
    asm volatile("cp.async.wait_group 1;" ::: "memory");
}
__device__ __forceinline__ void ldm4(uint32_t* r, uint32_t addr) {
    asm volatile("ldmatrix.sync.aligned.m8n8.x4.shared.b16 {%0,%1,%2,%3}, [%4];"
                 : "=r"(r[0]), "=r"(r[1]), "=r"(r[2]), "=r"(r[3]) : "r"(addr));
}
__device__ __forceinline__ void mma16816(float* c, const uint32_t* a, const uint32_t* b) {
    asm volatile("mma.sync.aligned.m16n8k16.row.col.f32.bf16.bf16.f32 "
                 "{%0,%1,%2,%3}, {%4,%5,%6,%7}, {%8,%9}, {%0,%1,%2,%3};"
                 : "+f"(c[0]), "+f"(c[1]), "+f"(c[2]), "+f"(c[3])
                 : "r"(a[0]), "r"(a[1]), "r"(a[2]), "r"(a[3]), "r"(b[0]), "r"(b[1]));
}
__device__ __forceinline__ uint32_t pk(__nv_bfloat16 a, __nv_bfloat16 b) {
    return ((uint32_t)__bfloat16_as_ushort(b) << 16) | (uint32_t)__bfloat16_as_ushort(a);
}
__device__ __forceinline__ void redadd(float* p, float v) {
    asm volatile("red.global.add.f32 [%0], %1;" :: "l"(p), "f"(v) : "memory");
}
__device__ __forceinline__ void split4(float4 v, uint2& hi, uint2& lo) {
    __nv_bfloat16 h0 = __float2bfloat16(v.x), h1 = __float2bfloat16(v.y);
    __nv_bfloat16 h2 = __float2bfloat16(v.z), h3 = __float2bfloat16(v.w);
    __nv_bfloat16 l0 = __float2bfloat16(v.x - __bfloat162float(h0));
    __nv_bfloat16 l1 = __float2bfloat16(v.y - __bfloat162float(h1));
    __nv_bfloat16 l2 = __float2bfloat16(v.z - __bfloat162float(h2));
    __nv_bfloat16 l3 = __float2bfloat16(v.w - __bfloat162float(h3));
    hi = make_uint2(pk(h0, h1), pk(h2, h3));
    lo = make_uint2(pk(l0, l1), pk(l2, l3));
}

// ---------------- small kernels ----------------
__global__ void zero_kernel(float* __restrict__ out, int n) {
    int i = blockIdx.x * blockDim.x + threadIdx.x;
    if (i < n) out[i] = 0.0f;
    if (blockIdx.x == 0 && threadIdx.x < NE) {
        g_count[threadIdx.x] = 0;
        g_probsum[threadIdx.x] = 0.0f;
    }
}

__global__ void convx_kernel(const float* __restrict__ x) {
    int i = blockIdx.x * 256 + threadIdx.x;
    float4 v = ((const float4*)x)[i];
    uint2 hi, lo;
    split4(v, hi, lo);
    ((uint2*)g_XH)[i] = hi;
    ((uint2*)g_XL)[i] = lo;
}

__global__ void convw13_kernel(const float* __restrict__ w1, const float* __restrict__ w3) {
    int i = blockIdx.x * 256 + threadIdx.x;
    int c4   = i & (DIM / 4 - 1);
    int rowe = i >> 8;
    int row  = rowe % HP;
    int e    = rowe / HP;
    float4 v1 = make_float4(0,0,0,0), v3 = make_float4(0,0,0,0);
    if (row < HID) {
        size_t si = (((size_t)e * HID + row) * DIM) / 4 + c4;
        v1 = ((const float4*)w1)[si];
        v3 = ((const float4*)w3)[si];
    }
    uint2 h, l;
    split4(v1, h, l); ((uint2*)g_W1H)[i] = h; ((uint2*)g_W1L)[i] = l;
    split4(v3, h, l); ((uint2*)g_W3H)[i] = h; ((uint2*)g_W3L)[i] = l;
}

__global__ void convw2_kernel(const float* __restrict__ w2) {
    int i = blockIdx.x * 256 + threadIdx.x;
    int c4   = i % (HP / 4);
    int rowd = i / (HP / 4);
    int col = c4 * 4;
    float4 v = make_float4(0,0,0,0);
    const float* src = w2 + (size_t)rowd * HID + col;
    if (col + 3 < HID) {
        v.x = src[0]; v.y = src[1]; v.z = src[2]; v.w = src[3];
    } else if (col < HID) {
        v.x = src[0];
        if (col + 1 < HID) v.y = src[1];
    }
    uint2 h, l;
    split4(v, h, l);
    ((uint2*)g_W2H)[i] = h;
    ((uint2*)g_W2L)[i] = l;
}

__global__ void router_kernel(const float* __restrict__ x, const float* __restrict__ gw) {
    int warp = (blockIdx.x * blockDim.x + threadIdx.x) >> 5;
    int lane = threadIdx.x & 31;
    if (warp >= TOKENS) return;
    const float* xr = x + (size_t)warp * DIM;
    float acc[NE];
#pragma unroll
    for (int e = 0; e < NE; e++) acc[e] = 0.0f;
    for (int i = lane; i < DIM; i += 32) {
        float xv = xr[i];
#pragma unroll
        for (int e = 0; e < NE; e++) acc[e] = fmaf(xv, gw[e * DIM + i], acc[e]);
    }
#pragma unroll
    for (int e = 0; e < NE; e++)
#pragma unroll
        for (int o = 16; o; o >>= 1) acc[e] += __shfl_xor_sync(0xffffffffu, acc[e], o);
    if (lane == 0) {
        float m = acc[0];
#pragma unroll
        for (int e = 1; e < NE; e++) m = fmaxf(m, acc[e]);
        float p[NE]; float s = 0.0f;
#pragma unroll
        for (int e = 0; e < NE; e++) { p[e] = __expf(acc[e] - m); s += p[e]; }
        float inv = 1.0f / s;
#pragma unroll
        for (int e = 0; e < NE; e++) p[e] *= inv;
        int i0 = 0;
#pragma unroll
        for (int e = 1; e < NE; e++) if (p[e] > p[i0]) i0 = e;
        int i1 = (i0 == 0) ? 1 : 0;
#pragma unroll
        for (int e = 0; e < NE; e++) if (e != i0 && p[e] > p[i1]) i1 = e;
        float s2 = p[i0] + p[i1];
        int pos0 = atomicAdd(&g_count[i0], 1);
        g_tokens[i0][pos0] = warp; g_wts[i0][pos0] = p[i0] / s2;
        int pos1 = atomicAdd(&g_count[i1], 1);
        g_tokens[i1][pos1] = warp; g_wts[i1][pos1] = p[i1] / s2;
#pragma unroll
        for (int e = 0; e < NE; e++) atomicAdd(&g_probsum[e], p[e]);
    }
}

__global__ void scan_kernel() {
    if (threadIdx.x == 0) {
        int s = 0;
#pragma unroll
        for (int e = 0; e < NE; e++) { g_off[e] = s; s += g_count[e]; }
    }
}

__global__ void aux_kernel(float* __restrict__ out, int out_size) {
    if (threadIdx.x == 0 && blockIdx.x == 0) {
        float s = 0.0f;
#pragma unroll
        for (int e = 0; e < NE; e++) {
            float tpe = g_probsum[e] / (float)TOKENS;
            float d = tpe - (1.0f / NE);
            s += d * d;
        }
        if (out_size > TOKENS * DIM) out[TOKENS * DIM] = 0.01f * (s / (float)NE);
    }
}

// ---------------- GEMM1: CTA 256x64, warp 64x32 dual ----------------
__global__ __launch_bounds__(256, 1) void gemm1_kernel() {
    int e = blockIdx.z;
    int cnt = g_count[e];
    int m0 = blockIdx.y * BM1;
    if (m0 >= cnt) return;
    int n0 = blockIdx.x * BN1;

    extern __shared__ char smraw[];
    uint32_t smb = s2u(smraw);
    int tid = threadIdx.x, wid = tid >> 5, lane = tid & 31;

    int rA = tid >> 3, c16 = tid & 7;
    uint32_t dstA[8], aoff[8];
#pragma unroll
    for (int i = 0; i < 8; i++) {
        int r = rA + 32 * i;
        dstA[i] = SWZ((uint32_t)(r * 128 + c16 * 16));
        int mi = m0 + r; if (mi >= cnt) mi = cnt - 1;
        aoff[i] = (uint32_t)((g_tokens[e][mi] * DIM + c16 * 8) * 2);
    }
    uint32_t dstB[2], boff[2];
#pragma unroll
    for (int i = 0; i < 2; i++) {
        int r = rA + 32 * i;
        dstB[i] = SWZ((uint32_t)(r * 128 + c16 * 16));
        boff[i] = (uint32_t)((((e * HP) + n0 + r) * DIM + c16 * 8) * 2);
    }

    auto load = [&](int kc, int s) {
        uint32_t base = smb + s * ST1;
        uint32_t ko = (uint32_t)kc * 128;
#pragma unroll
        for (int i = 0; i < 8; i++) {
            cpa16(base + dstA[i],         (const char*)g_XH + aoff[i] + ko);
            cpa16(base + 32768 + dstA[i], (const char*)g_XL + aoff[i] + ko);
        }
#pragma unroll
        for (int i = 0; i < 2; i++) {
            cpa16(base + 65536 + dstB[i], (const char*)g_W1H + boff[i] + ko);
            cpa16(base + 73728 + dstB[i], (const char*)g_W1L + boff[i] + ko);
            cpa16(base + 81920 + dstB[i], (const char*)g_W3H + boff[i] + ko);
            cpa16(base + 90112 + dstB[i], (const char*)g_W3L + boff[i] + ko);
        }
        cp_commit();
    };

    float c1[4][4][4], c3[4][4][4];
#pragma unroll
    for (int a = 0; a < 4; a++)
#pragma unroll
        for (int b = 0; b < 4; b++)
#pragma unroll
            for (int q = 0; q < 4; q++) { c1[a][b][q] = 0.0f; c3[a][b][q] = 0.0f; }

    int m0w = (wid & 3) * 64;
    int n0w = (wid >> 2) * 32;
    const int NC = DIM / 64;                    // 16

    load(0, 0); load(1, 1);

#pragma unroll 1
    for (int c = 0; c < NC; c++) {
        cp_wait1();
        __syncthreads();
        uint32_t bA = smb + (c & 1) * ST1;
#pragma unroll
        for (int ks = 0; ks < 4; ks++) {
            int k0b = ks * 32;
            uint32_t ah[4][4], al_[4][4];
#pragma unroll
            for (int mg = 0; mg < 4; mg++) {
                int row = m0w + mg * 16 + (lane & 15);
                uint32_t off = SWZ((uint32_t)(row * 128 + k0b + (lane >> 4) * 16));
                ldm4(ah[mg], bA + off);
                ldm4(al_[mg], bA + 32768 + off);
            }
#pragma unroll
            for (int g = 0; g < 2; g++) {
                int nrow = n0w + g * 16 + (lane & 7) + (lane >> 4) * 8;
                uint32_t bo = SWZ((uint32_t)(nrow * 128 + k0b + ((lane >> 3) & 1) * 16));
                uint32_t f1h[4], f1l[4], f3h[4], f3l[4];
                ldm4(f1h, bA + 65536 + bo); ldm4(f1l, bA + 73728 + bo);
                ldm4(f3h, bA + 81920 + bo); ldm4(f3l, bA + 90112 + bo);
#pragma unroll
                for (int mg = 0; mg < 4; mg++) {
#pragma unroll
                    for (int sub = 0; sub < 2; sub++) {
                        int ng = g * 2 + sub;
                        mma16816(c1[mg][ng], ah[mg],  f1h + sub * 2);
                        mma16816(c1[mg][ng], ah[mg],  f1l + sub * 2);
                        mma16816(c1[mg][ng], al_[mg], f1h + sub * 2);
                        mma16816(c3[mg][ng], ah[mg],  f3h + sub * 2);
                        mma16816(c3[mg][ng], ah[mg],  f3l + sub * 2);
                        mma16816(c3[mg][ng], al_[mg], f3h + sub * 2);
                    }
                }
            }
        }
        __syncthreads();
        if (c + 2 < NC) load(c + 2, c & 1);
        else cp_commit();
    }

    int goff = g_off[e];
    int t4 = lane >> 2, cpair = (lane & 3) * 2;
#pragma unroll
    for (int mg = 0; mg < 4; mg++) {
#pragma unroll
        for (int half = 0; half < 2; half++) {
            int mi = m0 + m0w + mg * 16 + half * 8 + t4;
            if (mi >= cnt) continue;
            size_t hb = (size_t)(goff + mi) * HP;
#pragma unroll
            for (int ng = 0; ng < 4; ng++) {
                int col = n0 + n0w + ng * 8 + cpair;
                float a0 = c1[mg][ng][half * 2 + 0];
                float a1 = c1[mg][ng][half * 2 + 1];
                float b0 = c3[mg][ng][half * 2 + 0];
                float b1 = c3[mg][ng][half * 2 + 1];
                float h0 = (a0 / (1.0f + __expf(-a0))) * b0;
                float h1 = (a1 / (1.0f + __expf(-a1))) * b1;
                __nv_bfloat16 h0h = __float2bfloat16(h0);
                __nv_bfloat16 h1h = __float2bfloat16(h1);
                __nv_bfloat16 h0l = __float2bfloat16(h0 - __bfloat162float(h0h));
                __nv_bfloat16 h1l = __float2bfloat16(h1 - __bfloat162float(h1h));
                *(uint32_t*)(g_HH + hb + col) = pk(h0h, h1h);
                *(uint32_t*)(g_HL + hb + col) = pk(h0l, h1l);
            }
        }
    }
}

// ---------------- GEMM2: CTA 256x128, warp 64x64 ----------------
__global__ __launch_bounds__(256, 1) void gemm2_kernel(float* __restrict__ out) {
    int e = blockIdx.z;
    int cnt = g_count[e];
    int m0 = blockIdx.y * BM2;
    if (m0 >= cnt) return;
    int n0 = blockIdx.x * BN2;

    extern __shared__ char smraw[];
    uint32_t smb = s2u(smraw);
    int tid = threadIdx.x, wid = tid >> 5, lane = tid & 31;
    int off_e = g_off[e];

    int rA = tid >> 3, c16 = tid & 7;
    uint32_t dstA[8], aoff[8];
#pragma unroll
    for (int i = 0; i < 8; i++) {
        int r = rA + 32 * i;
        dstA[i] = SWZ((uint32_t)(r * 128 + c16 * 16));
        int mi = m0 + r; if (mi >= cnt) mi = cnt - 1;
        aoff[i] = (uint32_t)(((off_e + mi) * HP + c16 * 8) * 2);
    }
    uint32_t dstB[4], boff[4];
#pragma unroll
    for (int i = 0; i < 4; i++) {
        int r = rA + 32 * i;
        dstB[i] = SWZ((uint32_t)(r * 128 + c16 * 16));
        boff[i] = (uint32_t)(((e * DIM + n0 + r) * HP + c16 * 8) * 2);
    }

    auto load = [&](int kc, int s) {
        uint32_t base = smb + s * ST2;
        uint32_t ko = (uint32_t)kc * 128;
#pragma unroll
        for (int i = 0; i < 8; i++) {
            cpa16(base + dstA[i],         (const char*)g_HH + aoff[i] + ko);
            cpa16(base + 32768 + dstA[i], (const char*)g_HL + aoff[i] + ko);
        }
#pragma unroll
        for (int i = 0; i < 4; i++) {
            cpa16(base + 65536 + dstB[i], (const char*)g_W2H + boff[i] + ko);
            cpa16(base + 81920 + dstB[i], (const char*)g_W2L + boff[i] + ko);
        }
        cp_commit();
    };

    float cc[4][8][4];
#pragma unroll
    for (int a = 0; a < 4; a++)
#pragma unroll
        for (int b = 0; b < 8; b++)
#pragma unroll
            for (int q = 0; q < 4; q++) cc[a][b][q] = 0.0f;

    int m0w = (wid & 3) * 64;
    int n0w = (wid >> 2) * 64;
    const int NC = HP / 64;                     // 44

    load(0, 0); load(1, 1);

#pragma unroll 1
    for (int c = 0; c < NC; c++) {
        cp_wait1();
        __syncthreads();
        uint32_t bA = smb + (c & 1) * ST2;
#pragma unroll
        for (int ks = 0; ks < 4; ks++) {
            int k0b = ks * 32;
            uint32_t ah[4][4], al_[4][4];
#pragma unroll
            for (int mg = 0; mg < 4; mg++) {
                int row = m0w + mg * 16 + (lane & 15);
                uint32_t off = SWZ((uint32_t)(row * 128 + k0b + (lane >> 4) * 16));
                ldm4(ah[mg], bA + off);
                ldm4(al_[mg], bA + 32768 + off);
            }
#pragma unroll
            for (int g = 0; g < 4; g++) {
                int nrow = n0w + g * 16 + (lane & 7) + (lane >> 4) * 8;
                uint32_t bo = SWZ((uint32_t)(nrow * 128 + k0b + ((lane >> 3) & 1) * 16));
                uint32_t fh[4], fl[4];
                ldm4(fh, bA + 65536 + bo);
                ldm4(fl, bA + 81920 + bo);
#pragma unroll
                for (int mg = 0; mg < 4; mg++) {
#pragma unroll
                    for (int sub = 0; sub < 2; sub++) {
                        int ng = g * 2 + sub;
                        mma16816(cc[mg][ng], ah[mg],  fh + sub * 2);
                        mma16816(cc[mg][ng], ah[mg],  fl + sub * 2);
                        mma16816(cc[mg][ng], al_[mg], fh + sub * 2);
                    }
                }
            }
        }
        __syncthreads();
        if (c + 2 < NC) load(c + 2, c & 1);
        else cp_commit();
    }

    int t4 = lane >> 2, cpair = (lane & 3) * 2;
#pragma unroll
    for (int mg = 0; mg < 4; mg++) {
#pragma unroll
        for (int half = 0; half < 2; half++) {
            int mi = m0 + m0w + mg * 16 + half * 8 + t4;
            if (mi >= cnt) continue;
            int tok = g_tokens[e][mi];
            float wt = g_wts[e][mi];
            float* orow = out + (size_t)tok * DIM;
#pragma unroll
            for (int ng = 0; ng < 8; ng++) {
                int col = n0 + n0w + ng * 8 + cpair;
                redadd(&orow[col],     wt * cc[mg][ng][half * 2 + 0]);
                redadd(&orow[col + 1], wt * cc[mg][ng][half * 2 + 1]);
            }
        }
    }
}

// ---------------- launch ----------------
extern "C" void kernel_launch(void* const* d_in, const int* in_sizes, int n_in,
                              void* d_out, int out_size) {
    const float* x  = (const float*)d_in[0];
    const float* gw = (const float*)d_in[1];
    const float* w1 = (const float*)d_in[2];
    const float* w2 = (const float*)d_in[3];
    const float* w3 = (const float*)d_in[4];
    float* out = (float*)d_out;

    cudaFuncSetAttribute(gemm1_kernel, cudaFuncAttributeMaxDynamicSharedMemorySize, 2 * ST1);
    cudaFuncSetAttribute(gemm2_kernel, cudaFuncAttributeMaxDynamicSharedMemorySize, 2 * ST2);

    int nzero = out_size < TOKENS * DIM ? out_size : TOKENS * DIM;
    zero_kernel<<<(nzero + 255) / 256, 256>>>(out, nzero);
    convx_kernel<<<(TOKENS * DIM / 4) / 256, 256>>>(x);
    convw13_kernel<<<(NE * HP * DIM / 4) / 256, 256>>>(w1, w3);
    convw2_kernel<<<(NE * DIM * HP / 4) / 256, 256>>>(w2);
    router_kernel<<<TOKENS * 32 / 256, 256>>>(x, gw);
    scan_kernel<<<1, 32>>>();

    dim3 g1(HP / BN1, TOKENS / BM1, NE);
    gemm1_kernel<<<g1, 256, 2 * ST1>>>();

    dim3 g2(DIM / BN2, TOKENS / BM2, NE);
    gemm2_kernel<<<g2, 256, 2 * ST2>>>(out);

    aux_kernel<<<1, 32>>>(out, out_size);
}

// round 6
// speedup vs baseline: 1.4080x; 1.4080x over previous
#include <cuda_runtime.h>
#include <cuda_fp16.h>
#include <cstdint>

#define TOKENS 8192
#define DIM    1024
#define NE     8
#define HID    2730
#define HP     2816            // H row stride (128B-aligned rows)
#define KH     2752            // 43*64: effective K for GEMM2 / N extent for GEMM1
#define NPAIR  (TOKENS*2)
#define HROWS  (NPAIR + 128)

#define BM  128
#define SWZ(o) ((o) ^ (((o) >> 3) & 0x70))

#define ST1 49152   // GEMM1 stage: Ah 0, Al 16384, W1h 32768, W3h 40960
#define ST2 49152   // GEMM2 stage: Ah 0, Al 16384, Bh 32768
#define NSTG 3

// ---------------- device scratch ----------------
__device__ int   g_count[NE];
__device__ int   g_off[NE];
__device__ int   g_tokens[NE][TOKENS];
__device__ float g_wts[NE][TOKENS];
__device__ float g_probsum[NE];

__device__ __half g_XH[TOKENS*DIM];
__device__ __half g_XL[TOKENS*DIM];
__device__ __half g_W1H[NE*HP*DIM];
__device__ __half g_W3H[NE*HP*DIM];
__device__ __half g_W2H[NE*DIM*HP];
__device__ __half g_HH[(size_t)HROWS*HP];
__device__ __half g_HL[(size_t)HROWS*HP];

// ---------------- helpers ----------------
__device__ __forceinline__ uint32_t s2u(const void* p) {
    uint32_t a;
    asm("{ .reg .u64 t; cvta.to.shared.u64 t, %1; cvt.u32.u64 %0, t; }" : "=r"(a) : "l"(p));
    return a;
}
__device__ __forceinline__ void cpa16(uint32_t dst, const void* src) {
    asm volatile("cp.async.cg.shared.global [%0], [%1], 16;" :: "r"(dst), "l"(src));
}
__device__ __forceinline__ void cp_commit() {
    asm volatile("cp.async.commit_group;" ::: "memory");
}
__device__ __forceinline__ void cp_wait2() {
    asm volatile("cp.async.wait_group 2;" ::: "memory");
}
__device__ __forceinline__ void ldm4(uint32_t* r, uint32_t addr) {
    asm volatile("ldmatrix.sync.aligned.m8n8.x4.shared.b16 {%0,%1,%2,%3}, [%4];"
                 : "=r"(r[0]), "=r"(r[1]), "=r"(r[2]), "=r"(r[3]) : "r"(addr));
}
__device__ __forceinline__ void mma16816(float* c, const uint32_t* a, const uint32_t* b) {
    asm volatile("mma.sync.aligned.m16n8k16.row.col.f32.f16.f16.f32 "
                 "{%0,%1,%2,%3}, {%4,%5,%6,%7}, {%8,%9}, {%0,%1,%2,%3};"
                 : "+f"(c[0]), "+f"(c[1]), "+f"(c[2]), "+f"(c[3])
                 : "r"(a[0]), "r"(a[1]), "r"(a[2]), "r"(a[3]), "r"(b[0]), "r"(b[1]));
}
__device__ __forceinline__ uint32_t pkh(__half a, __half b) {
    return ((uint32_t)__half_as_ushort(b) << 16) | (uint32_t)__half_as_ushort(a);
}
__device__ __forceinline__ void redadd(float* p, float v) {
    asm volatile("red.global.add.f32 [%0], %1;" :: "l"(p), "f"(v) : "memory");
}
// split float4 into fp16 hi/lo packed uint2
__device__ __forceinline__ void split4h(float4 v, uint2& hi, uint2& lo) {
    __half h0 = __float2half(v.x), h1 = __float2half(v.y);
    __half h2 = __float2half(v.z), h3 = __float2half(v.w);
    __half l0 = __float2half(v.x - __half2float(h0));
    __half l1 = __float2half(v.y - __half2float(h1));
    __half l2 = __float2half(v.z - __half2float(h2));
    __half l3 = __float2half(v.w - __half2float(h3));
    hi = make_uint2(pkh(h0, h1), pkh(h2, h3));
    lo = make_uint2(pkh(l0, l1), pkh(l2, l3));
}
__device__ __forceinline__ uint2 round4h(float4 v) {
    return make_uint2(pkh(__float2half(v.x), __float2half(v.y)),
                      pkh(__float2half(v.z), __float2half(v.w)));
}

// ---------------- small kernels ----------------
__global__ void zero_kernel(float* __restrict__ out, int n) {
    int i = blockIdx.x * blockDim.x + threadIdx.x;
    if (i < n) out[i] = 0.0f;
    if (blockIdx.x == 0 && threadIdx.x < NE) {
        g_count[threadIdx.x] = 0;
        g_probsum[threadIdx.x] = 0.0f;
    }
}

__global__ void convx_kernel(const float* __restrict__ x) {
    int i = blockIdx.x * 256 + threadIdx.x;
    float4 v = ((const float4*)x)[i];
    uint2 hi, lo;
    split4h(v, hi, lo);
    ((uint2*)g_XH)[i] = hi;
    ((uint2*)g_XL)[i] = lo;
}

__global__ void convw13_kernel(const float* __restrict__ w1, const float* __restrict__ w3) {
    int i = blockIdx.x * 256 + threadIdx.x;          // over NE*HP*DIM/4
    int c4   = i & (DIM / 4 - 1);
    int rowe = i >> 8;
    int row  = rowe % HP;
    int e    = rowe / HP;
    float4 v1 = make_float4(0,0,0,0), v3 = make_float4(0,0,0,0);
    if (row < HID) {
        size_t si = (((size_t)e * HID + row) * DIM) / 4 + c4;
        v1 = ((const float4*)w1)[si];
        v3 = ((const float4*)w3)[si];
    }
    ((uint2*)g_W1H)[i] = round4h(v1);
    ((uint2*)g_W3H)[i] = round4h(v3);
}

__global__ void convw2_kernel(const float* __restrict__ w2) {
    int i = blockIdx.x * 256 + threadIdx.x;          // over NE*DIM*HP/4
    int c4   = i % (HP / 4);
    int rowd = i / (HP / 4);
    int col = c4 * 4;
    float4 v = make_float4(0,0,0,0);
    const float* src = w2 + (size_t)rowd * HID + col;
    if (col + 3 < HID) {
        v.x = src[0]; v.y = src[1]; v.z = src[2]; v.w = src[3];
    } else if (col < HID) {
        v.x = src[0];
        if (col + 1 < HID) v.y = src[1];
    }
    ((uint2*)g_W2H)[i] = round4h(v);
}

__global__ void router_kernel(const float* __restrict__ x, const float* __restrict__ gw) {
    int warp = (blockIdx.x * blockDim.x + threadIdx.x) >> 5;
    int lane = threadIdx.x & 31;
    if (warp >= TOKENS) return;
    const float* xr = x + (size_t)warp * DIM;
    float acc[NE];
#pragma unroll
    for (int e = 0; e < NE; e++) acc[e] = 0.0f;
    for (int i = lane; i < DIM; i += 32) {
        float xv = xr[i];
#pragma unroll
        for (int e = 0; e < NE; e++) acc[e] = fmaf(xv, gw[e * DIM + i], acc[e]);
    }
#pragma unroll
    for (int e = 0; e < NE; e++)
#pragma unroll
        for (int o = 16; o; o >>= 1) acc[e] += __shfl_xor_sync(0xffffffffu, acc[e], o);
    if (lane == 0) {
        float m = acc[0];
#pragma unroll
        for (int e = 1; e < NE; e++) m = fmaxf(m, acc[e]);
        float p[NE]; float s = 0.0f;
#pragma unroll
        for (int e = 0; e < NE; e++) { p[e] = __expf(acc[e] - m); s += p[e]; }
        float inv = 1.0f / s;
#pragma unroll
        for (int e = 0; e < NE; e++) p[e] *= inv;
        int i0 = 0;
#pragma unroll
        for (int e = 1; e < NE; e++) if (p[e] > p[i0]) i0 = e;
        int i1 = (i0 == 0) ? 1 : 0;
#pragma unroll
        for (int e = 0; e < NE; e++) if (e != i0 && p[e] > p[i1]) i1 = e;
        float s2 = p[i0] + p[i1];
        int pos0 = atomicAdd(&g_count[i0], 1);
        g_tokens[i0][pos0] = warp; g_wts[i0][pos0] = p[i0] / s2;
        int pos1 = atomicAdd(&g_count[i1], 1);
        g_tokens[i1][pos1] = warp; g_wts[i1][pos1] = p[i1] / s2;
#pragma unroll
        for (int e = 0; e < NE; e++) atomicAdd(&g_probsum[e], p[e]);
    }
}

__global__ void scan_kernel() {
    if (threadIdx.x == 0) {
        int s = 0;
#pragma unroll
        for (int e = 0; e < NE; e++) { g_off[e] = s; s += g_count[e]; }
    }
}

__global__ void aux_kernel(float* __restrict__ out, int out_size) {
    if (threadIdx.x == 0 && blockIdx.x == 0) {
        float s = 0.0f;
#pragma unroll
        for (int e = 0; e < NE; e++) {
            float tpe = g_probsum[e] / (float)TOKENS;
            float d = tpe - (1.0f / NE);
            s += d * d;
        }
        if (out_size > TOKENS * DIM) out[TOKENS * DIM] = 0.01f * (s / (float)NE);
    }
}

// ---------------- GEMM1: CTA 128x64, warp 32x32 dual, fp16 2-pass ----------------
__global__ __launch_bounds__(256, 1) void gemm1_kernel() {
    int e = blockIdx.z;
    int cnt = g_count[e];
    int m0 = blockIdx.y * BM;
    if (m0 >= cnt) return;
    int n0 = blockIdx.x * 64;

    extern __shared__ char smraw[];
    uint32_t smb = s2u(smraw);
    int tid = threadIdx.x, wid = tid >> 5, lane = tid & 31;

    int rA = tid >> 3, c16 = tid & 7;
    uint32_t dstA[4], aoff[4];
#pragma unroll
    for (int i = 0; i < 4; i++) {
        int r = rA + 32 * i;
        dstA[i] = SWZ((uint32_t)(r * 128 + c16 * 16));
        int mi = m0 + r; if (mi >= cnt) mi = cnt - 1;
        aoff[i] = (uint32_t)((g_tokens[e][mi] * DIM + c16 * 8) * 2);
    }
    uint32_t dstB[2], boff[2];
#pragma unroll
    for (int i = 0; i < 2; i++) {
        int r = rA + 32 * i;
        dstB[i] = SWZ((uint32_t)(r * 128 + c16 * 16));
        boff[i] = (uint32_t)(((e * HP + n0 + r) * DIM + c16 * 8) * 2);
    }

    auto load = [&](int kc, int s) {
        uint32_t base = smb + s * ST1;
        uint32_t ko = (uint32_t)kc * 128;
#pragma unroll
        for (int i = 0; i < 4; i++) {
            cpa16(base + dstA[i],         (const char*)g_XH + aoff[i] + ko);
            cpa16(base + 16384 + dstA[i], (const char*)g_XL + aoff[i] + ko);
        }
#pragma unroll
        for (int i = 0; i < 2; i++) {
            cpa16(base + 32768 + dstB[i], (const char*)g_W1H + boff[i] + ko);
            cpa16(base + 40960 + dstB[i], (const char*)g_W3H + boff[i] + ko);
        }
        cp_commit();
    };

    float c1[2][4][4], c3[2][4][4];
#pragma unroll
    for (int a = 0; a < 2; a++)
#pragma unroll
        for (int b = 0; b < 4; b++)
#pragma unroll
            for (int q = 0; q < 4; q++) { c1[a][b][q] = 0.0f; c3[a][b][q] = 0.0f; }

    int m0w = (wid & 3) * 32;
    int n0w = (wid >> 2) * 32;
    const int NC = DIM / 64;                    // 16

    load(0, 0); load(1, 1); load(2, 2);

#pragma unroll 1
    for (int c = 0; c < NC; c++) {
        cp_wait2();
        __syncthreads();
        int st = c % NSTG;
        uint32_t bA = smb + st * ST1;
#pragma unroll
        for (int ks = 0; ks < 4; ks++) {
            int k0b = ks * 32;
            uint32_t ah[2][4], al_[2][4];
#pragma unroll
            for (int mg = 0; mg < 2; mg++) {
                int row = m0w + mg * 16 + (lane & 15);
                uint32_t off = SWZ((uint32_t)(row * 128 + k0b + (lane >> 4) * 16));
                ldm4(ah[mg], bA + off);
                ldm4(al_[mg], bA + 16384 + off);
            }
#pragma unroll
            for (int g = 0; g < 2; g++) {
                int nrow = n0w + g * 16 + (lane & 7) + (lane >> 4) * 8;
                uint32_t bo = SWZ((uint32_t)(nrow * 128 + k0b + ((lane >> 3) & 1) * 16));
                uint32_t f1h[4], f3h[4];
                ldm4(f1h, bA + 32768 + bo);
                ldm4(f3h, bA + 40960 + bo);
#pragma unroll
                for (int mg = 0; mg < 2; mg++) {
#pragma unroll
                    for (int sub = 0; sub < 2; sub++) {
                        int ng = g * 2 + sub;
                        mma16816(c1[mg][ng], ah[mg],  f1h + sub * 2);
                        mma16816(c1[mg][ng], al_[mg], f1h + sub * 2);
                        mma16816(c3[mg][ng], ah[mg],  f3h + sub * 2);
                        mma16816(c3[mg][ng], al_[mg], f3h + sub * 2);
                    }
                }
            }
        }
        __syncthreads();
        if (c + NSTG < NC) load(c + NSTG, st);
        else cp_commit();
    }

    // fused SwiGLU epilogue -> fp16 hi/lo H
    int goff = g_off[e];
    int t4 = lane >> 2, cpair = (lane & 3) * 2;
#pragma unroll
    for (int mg = 0; mg < 2; mg++) {
#pragma unroll
        for (int half = 0; half < 2; half++) {
            int mi = m0 + m0w + mg * 16 + half * 8 + t4;
            if (mi >= cnt) continue;
            size_t hb = (size_t)(goff + mi) * HP;
#pragma unroll
            for (int ng = 0; ng < 4; ng++) {
                int col = n0 + n0w + ng * 8 + cpair;
                float a0 = c1[mg][ng][half * 2 + 0];
                float a1 = c1[mg][ng][half * 2 + 1];
                float b0 = c3[mg][ng][half * 2 + 0];
                float b1 = c3[mg][ng][half * 2 + 1];
                float h0 = (a0 / (1.0f + __expf(-a0))) * b0;
                float h1 = (a1 / (1.0f + __expf(-a1))) * b1;
                __half h0h = __float2half(h0);
                __half h1h = __float2half(h1);
                __half h0l = __float2half(h0 - __half2float(h0h));
                __half h1l = __float2half(h1 - __half2float(h1h));
                *(uint32_t*)(g_HH + hb + col) = pkh(h0h, h1h);
                *(uint32_t*)(g_HL + hb + col) = pkh(h0l, h1l);
            }
        }
    }
}

// ---------------- GEMM2: CTA 128x128, warp 32x64, fp16 2-pass ----------------
__global__ __launch_bounds__(256, 1) void gemm2_kernel(float* __restrict__ out) {
    int e = blockIdx.z;
    int cnt = g_count[e];
    int m0 = blockIdx.y * BM;
    if (m0 >= cnt) return;
    int n0 = blockIdx.x * 128;

    extern __shared__ char smraw[];
    uint32_t smb = s2u(smraw);
    int tid = threadIdx.x, wid = tid >> 5, lane = tid & 31;
    int off_e = g_off[e];

    int rA = tid >> 3, c16 = tid & 7;
    uint32_t dstA[4], aoff[4], boff[4];
#pragma unroll
    for (int i = 0; i < 4; i++) {
        int r = rA + 32 * i;
        dstA[i] = SWZ((uint32_t)(r * 128 + c16 * 16));
        int mi = m0 + r; if (mi >= cnt) mi = cnt - 1;
        aoff[i] = (uint32_t)(((off_e + mi) * HP + c16 * 8) * 2);
        boff[i] = (uint32_t)(((e * DIM + n0 + r) * HP + c16 * 8) * 2);
    }

    auto load = [&](int kc, int s) {
        uint32_t base = smb + s * ST2;
        uint32_t ko = (uint32_t)kc * 128;
#pragma unroll
        for (int i = 0; i < 4; i++) {
            cpa16(base + dstA[i],         (const char*)g_HH + aoff[i] + ko);
            cpa16(base + 16384 + dstA[i], (const char*)g_HL + aoff[i] + ko);
            cpa16(base + 32768 + dstA[i], (const char*)g_W2H + boff[i] + ko);
        }
        cp_commit();
    };

    float cc[2][8][4];
#pragma unroll
    for (int a = 0; a < 2; a++)
#pragma unroll
        for (int b = 0; b < 8; b++)
#pragma unroll
            for (int q = 0; q < 4; q++) cc[a][b][q] = 0.0f;

    int m0w = (wid & 3) * 32;
    int n0w = (wid >> 2) * 64;
    const int NC = KH / 64;                     // 43

    load(0, 0); load(1, 1); load(2, 2);

#pragma unroll 1
    for (int c = 0; c < NC; c++) {
        cp_wait2();
        __syncthreads();
        int st = c % NSTG;
        uint32_t bA = smb + st * ST2;
#pragma unroll
        for (int ks = 0; ks < 4; ks++) {
            int k0b = ks * 32;
            uint32_t ah[2][4], al_[2][4];
#pragma unroll
            for (int mg = 0; mg < 2; mg++) {
                int row = m0w + mg * 16 + (lane & 15);
                uint32_t off = SWZ((uint32_t)(row * 128 + k0b + (lane >> 4) * 16));
                ldm4(ah[mg], bA + off);
                ldm4(al_[mg], bA + 16384 + off);
            }
#pragma unroll
            for (int g = 0; g < 4; g++) {
                int nrow = n0w + g * 16 + (lane & 7) + (lane >> 4) * 8;
                uint32_t bo = SWZ((uint32_t)(nrow * 128 + k0b + ((lane >> 3) & 1) * 16));
                uint32_t fh[4];
                ldm4(fh, bA + 32768 + bo);
#pragma unroll
                for (int mg = 0; mg < 2; mg++) {
#pragma unroll
                    for (int sub = 0; sub < 2; sub++) {
                        int ng = g * 2 + sub;
                        mma16816(cc[mg][ng], ah[mg],  fh + sub * 2);
                        mma16816(cc[mg][ng], al_[mg], fh + sub * 2);
                    }
                }
            }
        }
        __syncthreads();
        if (c + NSTG < NC) load(c + NSTG, st);
        else cp_commit();
    }

    int t4 = lane >> 2, cpair = (lane & 3) * 2;
#pragma unroll
    for (int mg = 0; mg < 2; mg++) {
#pragma unroll
        for (int half = 0; half < 2; half++) {
            int mi = m0 + m0w + mg * 16 + half * 8 + t4;
            if (mi >= cnt) continue;
            int tok = g_tokens[e][mi];
            float wt = g_wts[e][mi];
            float* orow = out + (size_t)tok * DIM;
#pragma unroll
            for (int ng = 0; ng < 8; ng++) {
                int col = n0 + n0w + ng * 8 + cpair;
                redadd(&orow[col],     wt * cc[mg][ng][half * 2 + 0]);
                redadd(&orow[col + 1], wt * cc[mg][ng][half * 2 + 1]);
            }
        }
    }
}

// ---------------- launch ----------------
extern "C" void kernel_launch(void* const* d_in, const int* in_sizes, int n_in,
                              void* d_out, int out_size) {
    const float* x  = (const float*)d_in[0];
    const float* gw = (const float*)d_in[1];
    const float* w1 = (const float*)d_in[2];
    const float* w2 = (const float*)d_in[3];
    const float* w3 = (const float*)d_in[4];
    float* out = (float*)d_out;

    cudaFuncSetAttribute(gemm1_kernel, cudaFuncAttributeMaxDynamicSharedMemorySize, NSTG * ST1);
    cudaFuncSetAttribute(gemm2_kernel, cudaFuncAttributeMaxDynamicSharedMemorySize, NSTG * ST2);

    int nzero = out_size < TOKENS * DIM ? out_size : TOKENS * DIM;
    zero_kernel<<<(nzero + 255) / 256, 256>>>(out, nzero);
    convx_kernel<<<(TOKENS * DIM / 4) / 256, 256>>>(x);
    convw13_kernel<<<(NE * HP * DIM / 4) / 256, 256>>>(w1, w3);
    convw2_kernel<<<(NE * DIM * HP / 4) / 256, 256>>>(w2);
    router_kernel<<<TOKENS * 32 / 256, 256>>>(x, gw);
    scan_kernel<<<1, 32>>>();

    dim3 g1(KH / 64, TOKENS / BM, NE);          // 43 x 64 x 8
    gemm1_kernel<<<g1, 256, NSTG * ST1>>>();

    dim3 g2(DIM / 128, TOKENS / BM, NE);        // 8 x 64 x 8
    gemm2_kernel<<<g2, 256, NSTG * ST2>>>(out);

    aux_kernel<<<1, 32>>>(out, out_size);
}

// round 7
// speedup vs baseline: 2.6002x; 1.8467x over previous
#include <cuda_runtime.h>
#include <cuda_fp16.h>
#include <cstdint>

#define TOKENS 8192
#define DIM    1024
#define NE     8
#define HID    2730
#define HP     2816            // H row stride (128B-aligned rows)
#define KH     2752            // 43*64 effective hidden extent
#define NPAIR  (TOKENS*2)
#define HROWS  (NPAIR + 128)

#define BM  128
#define SWZ(o) ((o) ^ (((o) >> 3) & 0x70))

#define ST1 32768   // GEMM1 stage: Ah 0 (16K), W1h 16384 (8K), W3h 24576 (8K)
#define ST2 32768   // GEMM2 stage: Ah 0 (16K), Bh 16384 (16K)
#define NSTG 3

// ---------------- device scratch ----------------
__device__ int   g_count[NE];
__device__ int   g_off[NE];
__device__ int   g_tokens[NE][TOKENS];
__device__ float g_wts[NE][TOKENS];
__device__ float g_probsum[NE];

__device__ __half g_XH[TOKENS*DIM];
__device__ __half g_W1H[NE*HP*DIM];
__device__ __half g_W3H[NE*HP*DIM];
__device__ __half g_W2H[NE*DIM*HP];
__device__ __half g_HH[(size_t)HROWS*HP];

// ---------------- helpers ----------------
__device__ __forceinline__ uint32_t s2u(const void* p) {
    uint32_t a;
    asm("{ .reg .u64 t; cvta.to.shared.u64 t, %1; cvt.u32.u64 %0, t; }" : "=r"(a) : "l"(p));
    return a;
}
__device__ __forceinline__ void cpa16(uint32_t dst, const void* src) {
    asm volatile("cp.async.cg.shared.global [%0], [%1], 16;" :: "r"(dst), "l"(src));
}
__device__ __forceinline__ void cp_commit() {
    asm volatile("cp.async.commit_group;" ::: "memory");
}
__device__ __forceinline__ void cp_wait2() {
    asm volatile("cp.async.wait_group 2;" ::: "memory");
}
__device__ __forceinline__ void ldm4(uint32_t* r, uint32_t addr) {
    asm volatile("ldmatrix.sync.aligned.m8n8.x4.shared.b16 {%0,%1,%2,%3}, [%4];"
                 : "=r"(r[0]), "=r"(r[1]), "=r"(r[2]), "=r"(r[3]) : "r"(addr));
}
__device__ __forceinline__ void mma16816(float* c, const uint32_t* a, const uint32_t* b) {
    asm volatile("mma.sync.aligned.m16n8k16.row.col.f32.f16.f16.f32 "
                 "{%0,%1,%2,%3}, {%4,%5,%6,%7}, {%8,%9}, {%0,%1,%2,%3};"
                 : "+f"(c[0]), "+f"(c[1]), "+f"(c[2]), "+f"(c[3])
                 : "r"(a[0]), "r"(a[1]), "r"(a[2]), "r"(a[3]), "r"(b[0]), "r"(b[1]));
}
__device__ __forceinline__ uint32_t pkh(__half a, __half b) {
    return ((uint32_t)__half_as_ushort(b) << 16) | (uint32_t)__half_as_ushort(a);
}
__device__ __forceinline__ void redadd(float* p, float v) {
    asm volatile("red.global.add.f32 [%0], %1;" :: "l"(p), "f"(v) : "memory");
}
__device__ __forceinline__ uint2 round4h(float4 v) {
    return make_uint2(pkh(__float2half(v.x), __float2half(v.y)),
                      pkh(__float2half(v.z), __float2half(v.w)));
}

// ---------------- small kernels ----------------
__global__ void zero_kernel(float* __restrict__ out, int n) {
    int i = blockIdx.x * blockDim.x + threadIdx.x;
    if (i < n) out[i] = 0.0f;
    if (blockIdx.x == 0 && threadIdx.x < NE) {
        g_count[threadIdx.x] = 0;
        g_probsum[threadIdx.x] = 0.0f;
    }
}

__global__ void convx_kernel(const float* __restrict__ x) {
    int i = blockIdx.x * 256 + threadIdx.x;
    float4 v = ((const float4*)x)[i];
    ((uint2*)g_XH)[i] = round4h(v);
}

__global__ void convw13_kernel(const float* __restrict__ w1, const float* __restrict__ w3) {
    int i = blockIdx.x * 256 + threadIdx.x;          // over NE*HP*DIM/4
    int c4   = i & (DIM / 4 - 1);
    int rowe = i >> 8;
    int row  = rowe % HP;
    int e    = rowe / HP;
    float4 v1 = make_float4(0,0,0,0), v3 = make_float4(0,0,0,0);
    if (row < HID) {
        size_t si = (((size_t)e * HID + row) * DIM) / 4 + c4;
        v1 = ((const float4*)w1)[si];
        v3 = ((const float4*)w3)[si];
    }
    ((uint2*)g_W1H)[i] = round4h(v1);
    ((uint2*)g_W3H)[i] = round4h(v3);
}

__global__ void convw2_kernel(const float* __restrict__ w2) {
    int i = blockIdx.x * 256 + threadIdx.x;          // over NE*DIM*HP/4
    int c4   = i % (HP / 4);
    int rowd = i / (HP / 4);
    int col = c4 * 4;
    float4 v = make_float4(0,0,0,0);
    const float* src = w2 + (size_t)rowd * HID + col;
    if (col + 3 < HID) {
        v.x = src[0]; v.y = src[1]; v.z = src[2]; v.w = src[3];
    } else if (col < HID) {
        v.x = src[0];
        if (col + 1 < HID) v.y = src[1];
    }
    ((uint2*)g_W2H)[i] = round4h(v);
}

__global__ void router_kernel(const float* __restrict__ x, const float* __restrict__ gw) {
    int warp = (blockIdx.x * blockDim.x + threadIdx.x) >> 5;
    int lane = threadIdx.x & 31;
    if (warp >= TOKENS) return;
    const float* xr = x + (size_t)warp * DIM;
    float acc[NE];
#pragma unroll
    for (int e = 0; e < NE; e++) acc[e] = 0.0f;
    for (int i = lane; i < DIM; i += 32) {
        float xv = xr[i];
#pragma unroll
        for (int e = 0; e < NE; e++) acc[e] = fmaf(xv, gw[e * DIM + i], acc[e]);
    }
#pragma unroll
    for (int e = 0; e < NE; e++)
#pragma unroll
        for (int o = 16; o; o >>= 1) acc[e] += __shfl_xor_sync(0xffffffffu, acc[e], o);
    if (lane == 0) {
        float m = acc[0];
#pragma unroll
        for (int e = 1; e < NE; e++) m = fmaxf(m, acc[e]);
        float p[NE]; float s = 0.0f;
#pragma unroll
        for (int e = 0; e < NE; e++) { p[e] = __expf(acc[e] - m); s += p[e]; }
        float inv = 1.0f / s;
#pragma unroll
        for (int e = 0; e < NE; e++) p[e] *= inv;
        int i0 = 0;
#pragma unroll
        for (int e = 1; e < NE; e++) if (p[e] > p[i0]) i0 = e;
        int i1 = (i0 == 0) ? 1 : 0;
#pragma unroll
        for (int e = 0; e < NE; e++) if (e != i0 && p[e] > p[i1]) i1 = e;
        float s2 = p[i0] + p[i1];
        int pos0 = atomicAdd(&g_count[i0], 1);
        g_tokens[i0][pos0] = warp; g_wts[i0][pos0] = p[i0] / s2;
        int pos1 = atomicAdd(&g_count[i1], 1);
        g_tokens[i1][pos1] = warp; g_wts[i1][pos1] = p[i1] / s2;
#pragma unroll
        for (int e = 0; e < NE; e++) atomicAdd(&g_probsum[e], p[e]);
    }
}

__global__ void scan_kernel() {
    if (threadIdx.x == 0) {
        int s = 0;
#pragma unroll
        for (int e = 0; e < NE; e++) { g_off[e] = s; s += g_count[e]; }
    }
}

__global__ void aux_kernel(float* __restrict__ out, int out_size) {
    if (threadIdx.x == 0 && blockIdx.x == 0) {
        float s = 0.0f;
#pragma unroll
        for (int e = 0; e < NE; e++) {
            float tpe = g_probsum[e] / (float)TOKENS;
            float d = tpe - (1.0f / NE);
            s += d * d;
        }
        if (out_size > TOKENS * DIM) out[TOKENS * DIM] = 0.01f * (s / (float)NE);
    }
}

// ---------------- GEMM1: CTA 128x64, warp 32x32 dual, fp16 1-pass ----------------
__global__ __launch_bounds__(256, 2) void gemm1_kernel() {
    int e = blockIdx.z;
    int cnt = g_count[e];
    int m0 = blockIdx.y * BM;
    if (m0 >= cnt) return;
    int n0 = blockIdx.x * 64;

    extern __shared__ char smraw[];
    uint32_t smb = s2u(smraw);
    int tid = threadIdx.x, wid = tid >> 5, lane = tid & 31;

    int rA = tid >> 3, c16 = tid & 7;
    uint32_t dstA[4], aoff[4];
#pragma unroll
    for (int i = 0; i < 4; i++) {
        int r = rA + 32 * i;
        dstA[i] = SWZ((uint32_t)(r * 128 + c16 * 16));
        int mi = m0 + r; if (mi >= cnt) mi = cnt - 1;
        aoff[i] = (uint32_t)((g_tokens[e][mi] * DIM + c16 * 8) * 2);
    }
    uint32_t dstB[2], boff[2];
#pragma unroll
    for (int i = 0; i < 2; i++) {
        int r = rA + 32 * i;
        dstB[i] = SWZ((uint32_t)(r * 128 + c16 * 16));
        boff[i] = (uint32_t)(((e * HP + n0 + r) * DIM + c16 * 8) * 2);
    }

    auto load = [&](int kc, int s) {
        uint32_t base = smb + s * ST1;
        uint32_t ko = (uint32_t)kc * 128;
#pragma unroll
        for (int i = 0; i < 4; i++)
            cpa16(base + dstA[i], (const char*)g_XH + aoff[i] + ko);
#pragma unroll
        for (int i = 0; i < 2; i++) {
            cpa16(base + 16384 + dstB[i], (const char*)g_W1H + boff[i] + ko);
            cpa16(base + 24576 + dstB[i], (const char*)g_W3H + boff[i] + ko);
        }
        cp_commit();
    };

    float c1[2][4][4], c3[2][4][4];
#pragma unroll
    for (int a = 0; a < 2; a++)
#pragma unroll
        for (int b = 0; b < 4; b++)
#pragma unroll
            for (int q = 0; q < 4; q++) { c1[a][b][q] = 0.0f; c3[a][b][q] = 0.0f; }

    int m0w = (wid & 3) * 32;
    int n0w = (wid >> 2) * 32;
    const int NC = DIM / 64;                    // 16

    load(0, 0); load(1, 1); load(2, 2);

#pragma unroll 1
    for (int c = 0; c < NC; c++) {
        cp_wait2();
        __syncthreads();
        int st = c % NSTG;
        uint32_t bA = smb + st * ST1;
#pragma unroll
        for (int ks = 0; ks < 4; ks++) {
            int k0b = ks * 32;
            uint32_t ah[2][4];
#pragma unroll
            for (int mg = 0; mg < 2; mg++) {
                int row = m0w + mg * 16 + (lane & 15);
                uint32_t off = SWZ((uint32_t)(row * 128 + k0b + (lane >> 4) * 16));
                ldm4(ah[mg], bA + off);
            }
#pragma unroll
            for (int g = 0; g < 2; g++) {
                int nrow = n0w + g * 16 + (lane & 7) + (lane >> 4) * 8;
                uint32_t bo = SWZ((uint32_t)(nrow * 128 + k0b + ((lane >> 3) & 1) * 16));
                uint32_t f1h[4], f3h[4];
                ldm4(f1h, bA + 16384 + bo);
                ldm4(f3h, bA + 24576 + bo);
#pragma unroll
                for (int mg = 0; mg < 2; mg++) {
#pragma unroll
                    for (int sub = 0; sub < 2; sub++) {
                        int ng = g * 2 + sub;
                        mma16816(c1[mg][ng], ah[mg], f1h + sub * 2);
                        mma16816(c3[mg][ng], ah[mg], f3h + sub * 2);
                    }
                }
            }
        }
        __syncthreads();
        if (c + NSTG < NC) load(c + NSTG, st);
        else cp_commit();
    }

    // fused SwiGLU epilogue -> fp16 H
    int goff = g_off[e];
    int t4 = lane >> 2, cpair = (lane & 3) * 2;
#pragma unroll
    for (int mg = 0; mg < 2; mg++) {
#pragma unroll
        for (int half = 0; half < 2; half++) {
            int mi = m0 + m0w + mg * 16 + half * 8 + t4;
            if (mi >= cnt) continue;
            size_t hb = (size_t)(goff + mi) * HP;
#pragma unroll
            for (int ng = 0; ng < 4; ng++) {
                int col = n0 + n0w + ng * 8 + cpair;
                float a0 = c1[mg][ng][half * 2 + 0];
                float a1 = c1[mg][ng][half * 2 + 1];
                float b0 = c3[mg][ng][half * 2 + 0];
                float b1 = c3[mg][ng][half * 2 + 1];
                float h0 = (a0 / (1.0f + __expf(-a0))) * b0;
                float h1 = (a1 / (1.0f + __expf(-a1))) * b1;
                *(uint32_t*)(g_HH + hb + col) = pkh(__float2half(h0), __float2half(h1));
            }
        }
    }
}

// ---------------- GEMM2: CTA 128x128, warp 32x64, fp16 1-pass ----------------
__global__ __launch_bounds__(256, 2) void gemm2_kernel(float* __restrict__ out) {
    int e = blockIdx.z;
    int cnt = g_count[e];
    int m0 = blockIdx.y * BM;
    if (m0 >= cnt) return;
    int n0 = blockIdx.x * 128;

    extern __shared__ char smraw[];
    uint32_t smb = s2u(smraw);
    int tid = threadIdx.x, wid = tid >> 5, lane = tid & 31;
    int off_e = g_off[e];

    int rA = tid >> 3, c16 = tid & 7;
    uint32_t dstA[4], aoff[4], boff[4];
#pragma unroll
    for (int i = 0; i < 4; i++) {
        int r = rA + 32 * i;
        dstA[i] = SWZ((uint32_t)(r * 128 + c16 * 16));
        int mi = m0 + r; if (mi >= cnt) mi = cnt - 1;
        aoff[i] = (uint32_t)(((off_e + mi) * HP + c16 * 8) * 2);
        boff[i] = (uint32_t)(((e * DIM + n0 + r) * HP + c16 * 8) * 2);
    }

    auto load = [&](int kc, int s) {
        uint32_t base = smb + s * ST2;
        uint32_t ko = (uint32_t)kc * 128;
#pragma unroll
        for (int i = 0; i < 4; i++) {
            cpa16(base + dstA[i],         (const char*)g_HH + aoff[i] + ko);
            cpa16(base + 16384 + dstA[i], (const char*)g_W2H + boff[i] + ko);
        }
        cp_commit();
    };

    float cc[2][8][4];
#pragma unroll
    for (int a = 0; a < 2; a++)
#pragma unroll
        for (int b = 0; b < 8; b++)
#pragma unroll
            for (int q = 0; q < 4; q++) cc[a][b][q] = 0.0f;

    int m0w = (wid & 3) * 32;
    int n0w = (wid >> 2) * 64;
    const int NC = KH / 64;                     // 43

    load(0, 0); load(1, 1); load(2, 2);

#pragma unroll 1
    for (int c = 0; c < NC; c++) {
        cp_wait2();
        __syncthreads();
        int st = c % NSTG;
        uint32_t bA = smb + st * ST2;
#pragma unroll
        for (int ks = 0; ks < 4; ks++) {
            int k0b = ks * 32;
            uint32_t ah[2][4];
#pragma unroll
            for (int mg = 0; mg < 2; mg++) {
                int row = m0w + mg * 16 + (lane & 15);
                uint32_t off = SWZ((uint32_t)(row * 128 + k0b + (lane >> 4) * 16));
                ldm4(ah[mg], bA + off);
            }
#pragma unroll
            for (int g = 0; g < 4; g++) {
                int nrow = n0w + g * 16 + (lane & 7) + (lane >> 4) * 8;
                uint32_t bo = SWZ((uint32_t)(nrow * 128 + k0b + ((lane >> 3) & 1) * 16));
                uint32_t fh[4];
                ldm4(fh, bA + 16384 + bo);
#pragma unroll
                for (int mg = 0; mg < 2; mg++) {
#pragma unroll
                    for (int sub = 0; sub < 2; sub++) {
                        int ng = g * 2 + sub;
                        mma16816(cc[mg][ng], ah[mg], fh + sub * 2);
                    }
                }
            }
        }
        __syncthreads();
        if (c + NSTG < NC) load(c + NSTG, st);
        else cp_commit();
    }

    int t4 = lane >> 2, cpair = (lane & 3) * 2;
#pragma unroll
    for (int mg = 0; mg < 2; mg++) {
#pragma unroll
        for (int half = 0; half < 2; half++) {
            int mi = m0 + m0w + mg * 16 + half * 8 + t4;
            if (mi >= cnt) continue;
            int tok = g_tokens[e][mi];
            float wt = g_wts[e][mi];
            float* orow = out + (size_t)tok * DIM;
#pragma unroll
            for (int ng = 0; ng < 8; ng++) {
                int col = n0 + n0w + ng * 8 + cpair;
                redadd(&orow[col],     wt * cc[mg][ng][half * 2 + 0]);
                redadd(&orow[col + 1], wt * cc[mg][ng][half * 2 + 1]);
            }
        }
    }
}

// ---------------- launch ----------------
extern "C" void kernel_launch(void* const* d_in, const int* in_sizes, int n_in,
                              void* d_out, int out_size) {
    const float* x  = (const float*)d_in[0];
    const float* gw = (const float*)d_in[1];
    const float* w1 = (const float*)d_in[2];
    const float* w2 = (const float*)d_in[3];
    const float* w3 = (const float*)d_in[4];
    float* out = (float*)d_out;

    cudaFuncSetAttribute(gemm1_kernel, cudaFuncAttributeMaxDynamicSharedMemorySize, NSTG * ST1);
    cudaFuncSetAttribute(gemm2_kernel, cudaFuncAttributeMaxDynamicSharedMemorySize, NSTG * ST2);

    int nzero = out_size < TOKENS * DIM ? out_size : TOKENS * DIM;
    zero_kernel<<<(nzero + 255) / 256, 256>>>(out, nzero);
    convx_kernel<<<(TOKENS * DIM / 4) / 256, 256>>>(x);
    convw13_kernel<<<(NE * HP * DIM / 4) / 256, 256>>>(w1, w3);
    convw2_kernel<<<(NE * DIM * HP / 4) / 256, 256>>>(w2);
    router_kernel<<<TOKENS * 32 / 256, 256>>>(x, gw);
    scan_kernel<<<1, 32>>>();

    dim3 g1(KH / 64, TOKENS / BM, NE);          // 43 x 64 x 8
    gemm1_kernel<<<g1, 256, NSTG * ST1>>>();

    dim3 g2(DIM / 128, TOKENS / BM, NE);        // 8 x 64 x 8
    gemm2_kernel<<<g2, 256, NSTG * ST2>>>(out);

    aux_kernel<<<1, 32>>>(out, out_size);
}

// round 11
// speedup vs baseline: 2.6820x; 1.0315x over previous
#include <cuda_runtime.h>
#include <cuda_fp16.h>
#include <cstdint>

#define TOKENS 8192
#define DIM    1024
#define NE     8
#define HID    2730
#define HP     2816
#define KH     2752
#define NPAIR  (TOKENS*2)
#define HROWS  (NPAIR + 128)

#define BM  128
#define SWZ(o) ((o) ^ (((o) >> 3) & 0x70))

#define ST1 32768
#define ST2 32768
#define NSTG 3

// ---------------- device scratch ----------------
__device__ int   g_count[NE];
__device__ int   g_off[NE];
__device__ int   g_tokens[NE][TOKENS];
__device__ float g_wts[NE][TOKENS];
__device__ float g_probsum[NE];

__device__ __half g_XH[TOKENS*DIM];
__device__ __half g_W1H[NE*HP*DIM];
__device__ __half g_W3H[NE*HP*DIM];
__device__ __half g_W2H[NE*DIM*HP];
__device__ __half g_HH[(size_t)HROWS*HP];

// ---------------- helpers ----------------
__device__ __forceinline__ uint32_t s2u(const void* p) {
    uint32_t a;
    asm("{ .reg .u64 t; cvta.to.shared.u64 t, %1; cvt.u32.u64 %0, t; }" : "=r"(a) : "l"(p));
    return a;
}
__device__ __forceinline__ void cpa16(uint32_t dst, const void* src) {
    asm volatile("cp.async.cg.shared.global [%0], [%1], 16;" :: "r"(dst), "l"(src));
}
__device__ __forceinline__ void cp_commit() {
    asm volatile("cp.async.commit_group;" ::: "memory");
}
__device__ __forceinline__ void cp_wait2() {
    asm volatile("cp.async.wait_group 2;" ::: "memory");
}
__device__ __forceinline__ void ldm4(uint32_t* r, uint32_t addr) {
    asm volatile("ldmatrix.sync.aligned.m8n8.x4.shared.b16 {%0,%1,%2,%3}, [%4];"
                 : "=r"(r[0]), "=r"(r[1]), "=r"(r[2]), "=r"(r[3]) : "r"(addr));
}
__device__ __forceinline__ void mma16816(float* c, const uint32_t* a, const uint32_t* b) {
    asm volatile("mma.sync.aligned.m16n8k16.row.col.f32.f16.f16.f32 "
                 "{%0,%1,%2,%3}, {%4,%5,%6,%7}, {%8,%9}, {%0,%1,%2,%3};"
                 : "+f"(c[0]), "+f"(c[1]), "+f"(c[2]), "+f"(c[3])
                 : "r"(a[0]), "r"(a[1]), "r"(a[2]), "r"(a[3]), "r"(b[0]), "r"(b[1]));
}
__device__ __forceinline__ uint32_t pkh(__half a, __half b) {
    return ((uint32_t)__half_as_ushort(b) << 16) | (uint32_t)__half_as_ushort(a);
}
__device__ __forceinline__ void redadd(float* p, float v) {
    asm volatile("red.global.add.f32 [%0], %1;" :: "l"(p), "f"(v) : "memory");
}
__device__ __forceinline__ uint2 round4h(float4 v) {
    return make_uint2(pkh(__float2half(v.x), __float2half(v.y)),
                      pkh(__float2half(v.z), __float2half(v.w)));
}

// ---------------- small kernels ----------------
__global__ void reset_kernel() {
    if (threadIdx.x < NE) {
        g_count[threadIdx.x] = 0;
        g_probsum[threadIdx.x] = 0.0f;
    }
}

__global__ void zeroout_kernel(float* __restrict__ out, int n) {
    int i = blockIdx.x * blockDim.x + threadIdx.x;
    if (i < n) out[i] = 0.0f;
}

__global__ void convx_kernel(const float* __restrict__ x) {
    int i = blockIdx.x * 256 + threadIdx.x;
    float4 v = ((const float4*)x)[i];
    ((uint2*)g_XH)[i] = round4h(v);
}

__global__ void convw13_kernel(const float* __restrict__ w1, const float* __restrict__ w3) {
    int i = blockIdx.x * 256 + threadIdx.x;
    int c4   = i & (DIM / 4 - 1);
    int rowe = i >> 8;
    int row  = rowe % HP;
    int e    = rowe / HP;
    float4 v1 = make_float4(0,0,0,0), v3 = make_float4(0,0,0,0);
    if (row < HID) {
        size_t si = (((size_t)e * HID + row) * DIM) / 4 + c4;
        v1 = ((const float4*)w1)[si];
        v3 = ((const float4*)w3)[si];
    }
    ((uint2*)g_W1H)[i] = round4h(v1);
    ((uint2*)g_W3H)[i] = round4h(v3);
}

__global__ void convw2_kernel(const float* __restrict__ w2) {
    int i = blockIdx.x * 256 + threadIdx.x;
    int c4   = i % (HP / 4);
    int rowd = i / (HP / 4);
    int col = c4 * 4;
    float4 v = make_float4(0,0,0,0);
    const float* src = w2 + (size_t)rowd * HID + col;
    if (col + 3 < HID) {
        v.x = src[0]; v.y = src[1]; v.z = src[2]; v.w = src[3];
    } else if (col < HID) {
        v.x = src[0];
        if (col + 1 < HID) v.y = src[1];
    }
    ((uint2*)g_W2H)[i] = round4h(v);
}

__global__ void router_kernel(const float* __restrict__ x, const float* __restrict__ gw) {
    int warp = (blockIdx.x * blockDim.x + threadIdx.x) >> 5;
    int lane = threadIdx.x & 31;
    if (warp >= TOKENS) return;
    const float* xr = x + (size_t)warp * DIM;
    float acc[NE];
#pragma unroll
    for (int e = 0; e < NE; e++) acc[e] = 0.0f;
    for (int i = lane; i < DIM; i += 32) {
        float xv = xr[i];
#pragma unroll
        for (int e = 0; e < NE; e++) acc[e] = fmaf(xv, gw[e * DIM + i], acc[e]);
    }
#pragma unroll
    for (int e = 0; e < NE; e++)
#pragma unroll
        for (int o = 16; o; o >>= 1) acc[e] += __shfl_xor_sync(0xffffffffu, acc[e], o);
    if (lane == 0) {
        float m = acc[0];
#pragma unroll
        for (int e = 1; e < NE; e++) m = fmaxf(m, acc[e]);
        float p[NE]; float s = 0.0f;
#pragma unroll
        for (int e = 0; e < NE; e++) { p[e] = __expf(acc[e] - m); s += p[e]; }
        float inv = 1.0f / s;
#pragma unroll
        for (int e = 0; e < NE; e++) p[e] *= inv;
        int i0 = 0;
#pragma unroll
        for (int e = 1; e < NE; e++) if (p[e] > p[i0]) i0 = e;
        int i1 = (i0 == 0) ? 1 : 0;
#pragma unroll
        for (int e = 0; e < NE; e++) if (e != i0 && p[e] > p[i1]) i1 = e;
        float s2 = p[i0] + p[i1];
        int pos0 = atomicAdd(&g_count[i0], 1);
        g_tokens[i0][pos0] = warp; g_wts[i0][pos0] = p[i0] / s2;
        int pos1 = atomicAdd(&g_count[i1], 1);
        g_tokens[i1][pos1] = warp; g_wts[i1][pos1] = p[i1] / s2;
#pragma unroll
        for (int e = 0; e < NE; e++) atomicAdd(&g_probsum[e], p[e]);
    }
}

__global__ void scan_kernel() {
    if (threadIdx.x == 0) {
        int s = 0;
#pragma unroll
        for (int e = 0; e < NE; e++) { g_off[e] = s; s += g_count[e]; }
    }
}

__global__ void aux_kernel(float* __restrict__ out, int out_size) {
    if (threadIdx.x == 0 && blockIdx.x == 0) {
        float s = 0.0f;
#pragma unroll
        for (int e = 0; e < NE; e++) {
            float tpe = g_probsum[e] / (float)TOKENS;
            float d = tpe - (1.0f / NE);
            s += d * d;
        }
        if (out_size > TOKENS * DIM) out[TOKENS * DIM] = 0.01f * (s / (float)NE);
    }
}

// ---------------- GEMM1: CTA 128x64, warp 32x32 dual, fp16 1-pass ----------------
__global__ __launch_bounds__(256, 2) void gemm1_kernel() {
    int e = blockIdx.z;
    int cnt = g_count[e];
    int m0 = blockIdx.y * BM;
    if (m0 >= cnt) return;
    int n0 = blockIdx.x * 64;

    extern __shared__ char smraw[];
    uint32_t smb = s2u(smraw);
    int tid = threadIdx.x, wid = tid >> 5, lane = tid & 31;

    int rA = tid >> 3, c16 = tid & 7;
    uint32_t dstA[4], aoff[4];
#pragma unroll
    for (int i = 0; i < 4; i++) {
        int r = rA + 32 * i;
        dstA[i] = SWZ((uint32_t)(r * 128 + c16 * 16));
        int mi = m0 + r; if (mi >= cnt) mi = cnt - 1;
        aoff[i] = (uint32_t)((g_tokens[e][mi] * DIM + c16 * 8) * 2);
    }
    uint32_t dstB[2], boff[2];
#pragma unroll
    for (int i = 0; i < 2; i++) {
        int r = rA + 32 * i;
        dstB[i] = SWZ((uint32_t)(r * 128 + c16 * 16));
        boff[i] = (uint32_t)(((e * HP + n0 + r) * DIM + c16 * 8) * 2);
    }

    auto load = [&](int kc, int s) {
        uint32_t base = smb + s * ST1;
        uint32_t ko = (uint32_t)kc * 128;
#pragma unroll
        for (int i = 0; i < 4; i++)
            cpa16(base + dstA[i], (const char*)g_XH + aoff[i] + ko);
#pragma unroll
        for (int i = 0; i < 2; i++) {
            cpa16(base + 16384 + dstB[i], (const char*)g_W1H + boff[i] + ko);
            cpa16(base + 24576 + dstB[i], (const char*)g_W3H + boff[i] + ko);
        }
        cp_commit();
    };

    float c1[2][4][4], c3[2][4][4];
#pragma unroll
    for (int a = 0; a < 2; a++)
#pragma unroll
        for (int b = 0; b < 4; b++)
#pragma unroll
            for (int q = 0; q < 4; q++) { c1[a][b][q] = 0.0f; c3[a][b][q] = 0.0f; }

    int m0w = (wid & 3) * 32;
    int n0w = (wid >> 2) * 32;
    const int NC = DIM / 64;                    // 16

    load(0, 0); load(1, 1); load(2, 2);

#pragma unroll 1
    for (int c = 0; c < NC; c++) {
        cp_wait2();
        __syncthreads();
        int st = c % NSTG;
        uint32_t bA = smb + st * ST1;
#pragma unroll
        for (int ks = 0; ks < 4; ks++) {
            int k0b = ks * 32;
            uint32_t ah[2][4];
#pragma unroll
            for (int mg = 0; mg < 2; mg++) {
                int row = m0w + mg * 16 + (lane & 15);
                uint32_t off = SWZ((uint32_t)(row * 128 + k0b + (lane >> 4) * 16));
                ldm4(ah[mg], bA + off);
            }
#pragma unroll
            for (int g = 0; g < 2; g++) {
                int nrow = n0w + g * 16 + (lane & 7) + (lane >> 4) * 8;
                uint32_t bo = SWZ((uint32_t)(nrow * 128 + k0b + ((lane >> 3) & 1) * 16));
                uint32_t f1h[4], f3h[4];
                ldm4(f1h, bA + 16384 + bo);
                ldm4(f3h, bA + 24576 + bo);
#pragma unroll
                for (int mg = 0; mg < 2; mg++) {
#pragma unroll
                    for (int sub = 0; sub < 2; sub++) {
                        int ng = g * 2 + sub;
                        mma16816(c1[mg][ng], ah[mg], f1h + sub * 2);
                        mma16816(c3[mg][ng], ah[mg], f3h + sub * 2);
                    }
                }
            }
        }
        __syncthreads();
        if (c + NSTG < NC) load(c + NSTG, st);
        else cp_commit();
    }

    int goff = g_off[e];
    int t4 = lane >> 2, cpair = (lane & 3) * 2;
#pragma unroll
    for (int mg = 0; mg < 2; mg++) {
#pragma unroll
        for (int half = 0; half < 2; half++) {
            int mi = m0 + m0w + mg * 16 + half * 8 + t4;
            if (mi >= cnt) continue;
            size_t hb = (size_t)(goff + mi) * HP;
#pragma unroll
            for (int ng = 0; ng < 4; ng++) {
                int col = n0 + n0w + ng * 8 + cpair;
                float a0 = c1[mg][ng][half * 2 + 0];
                float a1 = c1[mg][ng][half * 2 + 1];
                float b0 = c3[mg][ng][half * 2 + 0];
                float b1 = c3[mg][ng][half * 2 + 1];
                float h0 = (a0 / (1.0f + __expf(-a0))) * b0;
                float h1 = (a1 / (1.0f + __expf(-a1))) * b1;
                *(uint32_t*)(g_HH + hb + col) = pkh(__float2half(h0), __float2half(h1));
            }
        }
    }
}

// ---------------- GEMM2: CTA 128x128, warp 32x64, fp16 1-pass ----------------
__global__ __launch_bounds__(256, 2) void gemm2_kernel(float* __restrict__ out) {
    int e = blockIdx.z;
    int cnt = g_count[e];
    int m0 = blockIdx.y * BM;
    if (m0 >= cnt) return;
    int n0 = blockIdx.x * 128;

    extern __shared__ char smraw[];
    uint32_t smb = s2u(smraw);
    int tid = threadIdx.x, wid = tid >> 5, lane = tid & 31;
    int off_e = g_off[e];

    int rA = tid >> 3, c16 = tid & 7;
    uint32_t dstA[4], aoff[4], boff[4];
#pragma unroll
    for (int i = 0; i < 4; i++) {
        int r = rA + 32 * i;
        dstA[i] = SWZ((uint32_t)(r * 128 + c16 * 16));
        int mi = m0 + r; if (mi >= cnt) mi = cnt - 1;
        aoff[i] = (uint32_t)(((off_e + mi) * HP + c16 * 8) * 2);
        boff[i] = (uint32_t)(((e * DIM + n0 + r) * HP + c16 * 8) * 2);
    }

    auto load = [&](int kc, int s) {
        uint32_t base = smb + s * ST2;
        uint32_t ko = (uint32_t)kc * 128;
#pragma unroll
        for (int i = 0; i < 4; i++) {
            cpa16(base + dstA[i],         (const char*)g_HH + aoff[i] + ko);
            cpa16(base + 16384 + dstA[i], (const char*)g_W2H + boff[i] + ko);
        }
        cp_commit();
    };

    float cc[2][8][4];
#pragma unroll
    for (int a = 0; a < 2; a++)
#pragma unroll
        for (int b = 0; b < 8; b++)
#pragma unroll
            for (int q = 0; q < 4; q++) cc[a][b][q] = 0.0f;

    int m0w = (wid & 3) * 32;
    int n0w = (wid >> 2) * 64;
    const int NC = KH / 64;                     // 43

    load(0, 0); load(1, 1); load(2, 2);

#pragma unroll 1
    for (int c = 0; c < NC; c++) {
        cp_wait2();
        __syncthreads();
        int st = c % NSTG;
        uint32_t bA = smb + st * ST2;
#pragma unroll
        for (int ks = 0; ks < 4; ks++) {
            int k0b = ks * 32;
            uint32_t ah[2][4];
#pragma unroll
            for (int mg = 0; mg < 2; mg++) {
                int row = m0w + mg * 16 + (lane & 15);
                uint32_t off = SWZ((uint32_t)(row * 128 + k0b + (lane >> 4) * 16));
                ldm4(ah[mg], bA + off);
            }
#pragma unroll
            for (int g = 0; g < 4; g++) {
                int nrow = n0w + g * 16 + (lane & 7) + (lane >> 4) * 8;
                uint32_t bo = SWZ((uint32_t)(nrow * 128 + k0b + ((lane >> 3) & 1) * 16));
                uint32_t fh[4];
                ldm4(fh, bA + 16384 + bo);
#pragma unroll
                for (int mg = 0; mg < 2; mg++) {
#pragma unroll
                    for (int sub = 0; sub < 2; sub++) {
                        int ng = g * 2 + sub;
                        mma16816(cc[mg][ng], ah[mg], fh + sub * 2);
                    }
                }
            }
        }
        __syncthreads();
        if (c + NSTG < NC) load(c + NSTG, st);
        else cp_commit();
    }

    int t4 = lane >> 2, cpair = (lane & 3) * 2;
#pragma unroll
    for (int mg = 0; mg < 2; mg++) {
#pragma unroll
        for (int half = 0; half < 2; half++) {
            int mi = m0 + m0w + mg * 16 + half * 8 + t4;
            if (mi >= cnt) continue;
            int tok = g_tokens[e][mi];
            float wt = g_wts[e][mi];
            float* orow = out + (size_t)tok * DIM;
#pragma unroll
            for (int ng = 0; ng < 8; ng++) {
                int col = n0 + n0w + ng * 8 + cpair;
                redadd(&orow[col],     wt * cc[mg][ng][half * 2 + 0]);
                redadd(&orow[col + 1], wt * cc[mg][ng][half * 2 + 1]);
            }
        }
    }
}

// ---------------- launch (event-forked streams, capture-safe) ----------------
extern "C" void kernel_launch(void* const* d_in, const int* in_sizes, int n_in,
                              void* d_out, int out_size) {
    const float* x  = (const float*)d_in[0];
    const float* gw = (const float*)d_in[1];
    const float* w1 = (const float*)d_in[2];
    const float* w2 = (const float*)d_in[3];
    const float* w3 = (const float*)d_in[4];
    float* out = (float*)d_out;

    cudaFuncSetAttribute(gemm1_kernel, cudaFuncAttributeMaxDynamicSharedMemorySize, NSTG * ST1);
    cudaFuncSetAttribute(gemm2_kernel, cudaFuncAttributeMaxDynamicSharedMemorySize, NSTG * ST2);

    cudaStream_t s1, s2;
    cudaEvent_t evRoot, ev1, ev2;
    cudaStreamCreateWithFlags(&s1, cudaStreamNonBlocking);
    cudaStreamCreateWithFlags(&s2, cudaStreamNonBlocking);
    cudaEventCreateWithFlags(&evRoot, cudaEventDisableTiming);
    cudaEventCreateWithFlags(&ev1, cudaEventDisableTiming);
    cudaEventCreateWithFlags(&ev2, cudaEventDisableTiming);

    int nzero = out_size < TOKENS * DIM ? out_size : TOKENS * DIM;

    // fork point on base (null) stream
    cudaEventRecord(evRoot, 0);
    cudaStreamWaitEvent(s1, evRoot, 0);
    cudaStreamWaitEvent(s2, evRoot, 0);

    // base stream: routing chain (needed by gemm1)
    reset_kernel<<<1, 32>>>();
    router_kernel<<<TOKENS * 32 / 256, 256>>>(x, gw);
    scan_kernel<<<1, 32>>>();

    // s1: weight/x converts needed by gemm1
    convx_kernel<<<(TOKENS * DIM / 4) / 256, 256, 0, s1>>>(x);
    convw13_kernel<<<(NE * HP * DIM / 4) / 256, 256, 0, s1>>>(w1, w3);
    cudaEventRecord(ev1, s1);

    // s2: things needed only by gemm2 (hide under gemm1)
    zeroout_kernel<<<(nzero + 255) / 256, 256, 0, s2>>>(out, nzero);
    convw2_kernel<<<(NE * DIM * HP / 4) / 256, 256, 0, s2>>>(w2);
    cudaEventRecord(ev2, s2);

    // join s1 before gemm1
    cudaStreamWaitEvent(0, ev1, 0);
    dim3 g1(KH / 64, TOKENS / BM, NE);
    gemm1_kernel<<<g1, 256, NSTG * ST1>>>();

    // join s2 before gemm2
    cudaStreamWaitEvent(0, ev2, 0);
    dim3 g2(DIM / 128, TOKENS / BM, NE);
    gemm2_kernel<<<g2, 256, NSTG * ST2>>>(out);

    aux_kernel<<<1, 32>>>(out, out_size);

    cudaEventDestroy(evRoot);
    cudaEventDestroy(ev1);
    cudaEventDestroy(ev2);
    cudaStreamDestroy(s1);
    cudaStreamDestroy(s2);
}